// round 1
// baseline (speedup 1.0000x reference)
#include <cuda_runtime.h>
#include <math.h>

// Problem constants
#define B_   2
#define S_   2048
#define D_   1024
#define H_   16
#define HD_  64
#define F_   4096
#define NTOK (B_ * S_)          // 4096 tokens
#define EPSLN 1e-5f

// ---------------------------------------------------------------------------
// Scratch (device globals — allocation in kernel_launch is forbidden)
// ---------------------------------------------------------------------------
__device__ float g_qkv[NTOK * 3 * D_];   // [4096, 3072]
__device__ float g_ctx[NTOK * D_];       // [4096, 1024] attention context
__device__ float g_tmp[NTOK * D_];       // mha_out, then ffn_out
__device__ float g_agg[NTOK * D_];       // post-LN1 activations
__device__ float g_h1 [NTOK * F_];       // [4096, 4096] FFN hidden

// ---------------------------------------------------------------------------
// SGEMM:  C[M,N] = A[M,K] @ W[N,K]^T + bias[N]   (optional ReLU)
// Both A and W are row-major with K contiguous (exactly the torch Linear layout).
// 128x128 block tile, BK=16, 8x8 per thread, 256 threads.
// ---------------------------------------------------------------------------
#define BM 128
#define BN 128
#define BK 16
#define PADM 132   // smem row stride (floats): keeps float4 alignment, reduces
                   // transposed-store conflicts to 2-way

template<bool RELU>
__global__ __launch_bounds__(256, 2)
void sgemm_nt(const float* __restrict__ A, const float* __restrict__ W,
              const float* __restrict__ bias, float* __restrict__ C,
              int M, int N, int K) {
    __shared__ float As[BK][PADM];
    __shared__ float Ws[BK][PADM];

    const int tid = threadIdx.x;
    const int bm0 = blockIdx.y * BM;
    const int bn0 = blockIdx.x * BN;
    const int tx  = tid & 15;          // 0..15 -> N direction
    const int ty  = tid >> 4;          // 0..15 -> M direction

    float acc[8][8];
#pragma unroll
    for (int i = 0; i < 8; i++)
#pragma unroll
        for (int j = 0; j < 8; j++) acc[i][j] = 0.f;

    for (int kt = 0; kt < K; kt += BK) {
        // Load A tile (BM x BK) and W tile (BN x BK), transposed into smem.
        // 512 float4 per tile => 2 per thread per matrix.
#pragma unroll
        for (int it = 0; it < 2; it++) {
            int e   = tid + it * 256;       // 0..511
            int row = e >> 2;               // 0..127
            int kc  = (e & 3) * 4;          // 0,4,8,12
            float4 av = *(const float4*)&A[(size_t)(bm0 + row) * K + kt + kc];
            As[kc + 0][row] = av.x;
            As[kc + 1][row] = av.y;
            As[kc + 2][row] = av.z;
            As[kc + 3][row] = av.w;
            float4 wv = *(const float4*)&W[(size_t)(bn0 + row) * K + kt + kc];
            Ws[kc + 0][row] = wv.x;
            Ws[kc + 1][row] = wv.y;
            Ws[kc + 2][row] = wv.z;
            Ws[kc + 3][row] = wv.w;
        }
        __syncthreads();

#pragma unroll
        for (int k = 0; k < BK; k++) {
            float a[8], b[8];
            *(float4*)(a + 0) = *(const float4*)&As[k][ty * 8 + 0];
            *(float4*)(a + 4) = *(const float4*)&As[k][ty * 8 + 4];
            *(float4*)(b + 0) = *(const float4*)&Ws[k][tx * 8 + 0];
            *(float4*)(b + 4) = *(const float4*)&Ws[k][tx * 8 + 4];
#pragma unroll
            for (int i = 0; i < 8; i++)
#pragma unroll
                for (int j = 0; j < 8; j++)
                    acc[i][j] = fmaf(a[i], b[j], acc[i][j]);
        }
        __syncthreads();
    }

    // Epilogue: bias (+ReLU), vectorized store.
    float bv[8];
#pragma unroll
    for (int j = 0; j < 8; j++) bv[j] = bias[bn0 + tx * 8 + j];

#pragma unroll
    for (int i = 0; i < 8; i++) {
        float4 o0, o1;
        float r[8];
#pragma unroll
        for (int j = 0; j < 8; j++) {
            float v = acc[i][j] + bv[j];
            if (RELU) v = fmaxf(v, 0.f);
            r[j] = v;
        }
        o0.x = r[0]; o0.y = r[1]; o0.z = r[2]; o0.w = r[3];
        o1.x = r[4]; o1.y = r[5]; o1.z = r[6]; o1.w = r[7];
        float* cp = &C[(size_t)(bm0 + ty * 8 + i) * N + bn0 + tx * 8];
        *(float4*)(cp + 0) = o0;
        *(float4*)(cp + 4) = o1;
    }
}

// ---------------------------------------------------------------------------
// Flash attention, fp32. qkv layout per token row (3*D):
//   head h owns contiguous 192 floats: [q(64) | k(64) | v(64)].
// Br = Bc = 64, 256 threads, 4x4 micro-tile per thread. Online softmax.
// ctx written as [token, h*64 + d]  (== transpose(0,2,1,3).reshape).
// ---------------------------------------------------------------------------
#define FSTR 65   // smem row stride (bank-conflict mitigation)
#define FLASH_SMEM (4 * 64 * FSTR * 4)   // Qs,Ks,Vs,Ps

__global__ __launch_bounds__(256)
void flash_kernel(const float* __restrict__ qkv, float* __restrict__ ctx) {
    extern __shared__ float sm[];
    float* Qs = sm;
    float* Ks = Qs + 64 * FSTR;
    float* Vs = Ks + 64 * FSTR;
    float* Ps = Vs + 64 * FSTR;

    const int tid = threadIdx.x;
    const int bh  = blockIdx.y;
    const int b   = bh / H_;
    const int h   = bh % H_;
    const float* base = qkv + (size_t)b * S_ * (3 * D_) + h * (3 * HD_);
    const int q0 = blockIdx.x * 64;

    // Load Q tile (scaled by 1/sqrt(hd) = 0.125 here, once)
#pragma unroll
    for (int it = 0; it < 4; it++) {
        int e   = tid + 256 * it;        // 0..1023
        int row = e >> 4;                // 0..63
        int c   = (e & 15) * 4;          // 0..60
        float4 v = *(const float4*)(base + (size_t)(q0 + row) * (3 * D_) + c);
        Qs[row * FSTR + c + 0] = v.x * 0.125f;
        Qs[row * FSTR + c + 1] = v.y * 0.125f;
        Qs[row * FSTR + c + 2] = v.z * 0.125f;
        Qs[row * FSTR + c + 3] = v.w * 0.125f;
    }

    const int r0 = (tid >> 4) * 4;   // 4 query rows owned by this thread
    const int c0 = (tid & 15) * 4;   // 4 key-cols / 4 out-dims owned

    float m[4], l[4], acc[4][4];
#pragma unroll
    for (int i = 0; i < 4; i++) {
        m[i] = -INFINITY; l[i] = 0.f;
#pragma unroll
        for (int j = 0; j < 4; j++) acc[i][j] = 0.f;
    }

    for (int kt = 0; kt < S_; kt += 64) {
        __syncthreads();   // previous iteration's Ks/Vs/Ps readers done
        // Load K and V tiles
#pragma unroll
        for (int it = 0; it < 4; it++) {
            int e   = tid + 256 * it;
            int row = e >> 4;
            int c   = (e & 15) * 4;
            const float* kp = base + (size_t)(kt + row) * (3 * D_) + HD_ + c;
            float4 kv = *(const float4*)kp;
            Ks[row * FSTR + c + 0] = kv.x;
            Ks[row * FSTR + c + 1] = kv.y;
            Ks[row * FSTR + c + 2] = kv.z;
            Ks[row * FSTR + c + 3] = kv.w;
            float4 vv = *(const float4*)(kp + HD_);
            Vs[row * FSTR + c + 0] = vv.x;
            Vs[row * FSTR + c + 1] = vv.y;
            Vs[row * FSTR + c + 2] = vv.z;
            Vs[row * FSTR + c + 3] = vv.w;
        }
        __syncthreads();

        // Scores: s[i][j] = (Q/8)[r0+i, :] . K[c0+j, :]
        float s[4][4];
#pragma unroll
        for (int i = 0; i < 4; i++)
#pragma unroll
            for (int j = 0; j < 4; j++) s[i][j] = 0.f;

#pragma unroll 4
        for (int d = 0; d < 64; d++) {
            float q_[4], k_[4];
#pragma unroll
            for (int i = 0; i < 4; i++) q_[i] = Qs[(r0 + i) * FSTR + d];
#pragma unroll
            for (int j = 0; j < 4; j++) k_[j] = Ks[(c0 + j) * FSTR + d];
#pragma unroll
            for (int i = 0; i < 4; i++)
#pragma unroll
                for (int j = 0; j < 4; j++)
                    s[i][j] = fmaf(q_[i], k_[j], s[i][j]);
        }

        // Online softmax update per row (16 lanes share each row group)
#pragma unroll
        for (int i = 0; i < 4; i++) {
            float tm = fmaxf(fmaxf(s[i][0], s[i][1]), fmaxf(s[i][2], s[i][3]));
#pragma unroll
            for (int off = 8; off >= 1; off >>= 1)
                tm = fmaxf(tm, __shfl_xor_sync(0xffffffffu, tm, off));
            float mnew  = fmaxf(m[i], tm);
            float alpha = __expf(m[i] - mnew);
            float psum  = 0.f;
#pragma unroll
            for (int j = 0; j < 4; j++) {
                float p = __expf(s[i][j] - mnew);
                Ps[(r0 + i) * FSTR + c0 + j] = p;
                psum += p;
            }
#pragma unroll
            for (int off = 8; off >= 1; off >>= 1)
                psum += __shfl_xor_sync(0xffffffffu, psum, off);
            l[i] = l[i] * alpha + psum;
            m[i] = mnew;
#pragma unroll
            for (int dd = 0; dd < 4; dd++) acc[i][dd] *= alpha;
        }
        __syncthreads();   // P fully written before cross-thread reads

        // acc += P @ V
#pragma unroll 4
        for (int j = 0; j < 64; j++) {
            float v_[4], p_[4];
#pragma unroll
            for (int dd = 0; dd < 4; dd++) v_[dd] = Vs[j * FSTR + c0 + dd];
#pragma unroll
            for (int i = 0; i < 4; i++)  p_[i]  = Ps[(r0 + i) * FSTR + j];
#pragma unroll
            for (int i = 0; i < 4; i++)
#pragma unroll
                for (int dd = 0; dd < 4; dd++)
                    acc[i][dd] = fmaf(p_[i], v_[dd], acc[i][dd]);
        }
    }

    // Write context: ctx[(b*S + q0 + r), h*64 + c0 + dd] = acc / l
    float* op = ctx + ((size_t)(b * S_) + q0) * D_ + h * HD_;
#pragma unroll
    for (int i = 0; i < 4; i++) {
        float inv = 1.f / l[i];
        float4 o;
        o.x = acc[i][0] * inv;
        o.y = acc[i][1] * inv;
        o.z = acc[i][2] * inv;
        o.w = acc[i][3] * inv;
        *(float4*)&op[(size_t)(r0 + i) * D_ + c0] = o;
    }
}

// ---------------------------------------------------------------------------
// Fused residual + LayerNorm: out = LN(x + r) * g + b, one block per row
// ---------------------------------------------------------------------------
__global__ __launch_bounds__(256)
void add_ln_kernel(const float* __restrict__ x, const float* __restrict__ r,
                   const float* __restrict__ g, const float* __restrict__ bb,
                   float* __restrict__ out) {
    __shared__ float red[16];
    const int row = blockIdx.x;
    const int tid = threadIdx.x;

    float4 xv = ((const float4*)(x + (size_t)row * D_))[tid];
    float4 rv = ((const float4*)(r + (size_t)row * D_))[tid];
    float v0 = xv.x + rv.x, v1 = xv.y + rv.y, v2 = xv.z + rv.z, v3 = xv.w + rv.w;

    float s  = v0 + v1 + v2 + v3;
    float sq = v0 * v0 + v1 * v1 + v2 * v2 + v3 * v3;
#pragma unroll
    for (int o = 16; o >= 1; o >>= 1) {
        s  += __shfl_xor_sync(0xffffffffu, s,  o);
        sq += __shfl_xor_sync(0xffffffffu, sq, o);
    }
    int warp = tid >> 5, lane = tid & 31;
    if (lane == 0) { red[warp] = s; red[8 + warp] = sq; }
    __syncthreads();
    if (tid == 0) {
        float ts = 0.f, tq = 0.f;
#pragma unroll
        for (int i = 0; i < 8; i++) { ts += red[i]; tq += red[8 + i]; }
        float mean = ts * (1.0f / D_);
        float var  = tq * (1.0f / D_) - mean * mean;
        red[0] = mean;
        red[1] = rsqrtf(var + EPSLN);
    }
    __syncthreads();
    float mean = red[0], rstd = red[1];

    float4 gv = ((const float4*)g)[tid];
    float4 bv = ((const float4*)bb)[tid];
    float4 o;
    o.x = (v0 - mean) * rstd * gv.x + bv.x;
    o.y = (v1 - mean) * rstd * gv.y + bv.y;
    o.z = (v2 - mean) * rstd * gv.z + bv.z;
    o.w = (v3 - mean) * rstd * gv.w + bv.w;
    ((float4*)(out + (size_t)row * D_))[tid] = o;
}

// ---------------------------------------------------------------------------
// Host launcher
// ---------------------------------------------------------------------------
extern "C" void kernel_launch(void* const* d_in, const int* in_sizes, int n_in,
                              void* d_out, int out_size) {
    const float* src    = (const float*)d_in[0];
    const float* qkv_w  = (const float*)d_in[1];
    const float* qkv_b  = (const float*)d_in[2];
    const float* out_w  = (const float*)d_in[3];
    const float* out_b  = (const float*)d_in[4];
    const float* ffn_w1 = (const float*)d_in[5];
    const float* ffn_b1 = (const float*)d_in[6];
    const float* ffn_w2 = (const float*)d_in[7];
    const float* ffn_b2 = (const float*)d_in[8];
    const float* ln1_g  = (const float*)d_in[9];
    const float* ln1_b  = (const float*)d_in[10];
    const float* ln2_g  = (const float*)d_in[11];
    const float* ln2_b  = (const float*)d_in[12];
    float* out = (float*)d_out;

    float *qkv, *ctx, *tmp, *agg, *h1;
    cudaGetSymbolAddress((void**)&qkv, g_qkv);
    cudaGetSymbolAddress((void**)&ctx, g_ctx);
    cudaGetSymbolAddress((void**)&tmp, g_tmp);
    cudaGetSymbolAddress((void**)&agg, g_agg);
    cudaGetSymbolAddress((void**)&h1,  g_h1);

    cudaFuncSetAttribute(flash_kernel,
                         cudaFuncAttributeMaxDynamicSharedMemorySize, FLASH_SMEM);

    dim3 blk(256);

    // 1. QKV projection: [4096,1024] @ [3072,1024]^T -> [4096,3072]
    sgemm_nt<false><<<dim3((3 * D_) / BN, NTOK / BM), blk>>>(
        src, qkv_w, qkv_b, qkv, NTOK, 3 * D_, D_);

    // 2. Flash attention -> ctx [4096,1024]
    flash_kernel<<<dim3(S_ / 64, B_ * H_), blk, FLASH_SMEM>>>(qkv, ctx);

    // 3. Output projection -> tmp (mha_out)
    sgemm_nt<false><<<dim3(D_ / BN, NTOK / BM), blk>>>(
        ctx, out_w, out_b, tmp, NTOK, D_, D_);

    // 4. agg = LN1(src + mha_out)
    add_ln_kernel<<<NTOK, 256>>>(src, tmp, ln1_g, ln1_b, agg);

    // 5. FFN1 + ReLU -> h1 [4096,4096]
    sgemm_nt<true><<<dim3(F_ / BN, NTOK / BM), blk>>>(
        agg, ffn_w1, ffn_b1, h1, NTOK, F_, D_);

    // 6. FFN2 -> tmp (ffn_out)
    sgemm_nt<false><<<dim3(D_ / BN, NTOK / BM), blk>>>(
        h1, ffn_w2, ffn_b2, tmp, NTOK, D_, F_);

    // 7. out = LN2(agg + ffn_out)
    add_ln_kernel<<<NTOK, 256>>>(agg, tmp, ln2_g, ln2_b, out);
}

// round 5
// speedup vs baseline: 1.5148x; 1.5148x over previous
#include <cuda_runtime.h>
#include <cuda_bf16.h>
#include <math.h>
#include <stdint.h>

// Problem constants
#define B_   2
#define S_   2048
#define D_   1024
#define H_   16
#define HD_  64
#define F_   4096
#define NTOK (B_ * S_)
#define EPSLN 1e-5f

// ---------------------------------------------------------------------------
// Scratch (device globals)
// ---------------------------------------------------------------------------
__device__ float g_qkv[NTOK * 3 * D_];
__device__ float g_tmp[NTOK * D_];
__device__ float g_agg[NTOK * D_];
__device__ __nv_bfloat16 g_src_hi[NTOK * D_];
__device__ __nv_bfloat16 g_src_lo[NTOK * D_];
__device__ __nv_bfloat16 g_ctx_hi[NTOK * D_];
__device__ __nv_bfloat16 g_ctx_lo[NTOK * D_];
__device__ __nv_bfloat16 g_agg_hi[NTOK * D_];
__device__ __nv_bfloat16 g_agg_lo[NTOK * D_];
__device__ __nv_bfloat16 g_h1_hi[NTOK * F_];
__device__ __nv_bfloat16 g_h1_lo[NTOK * F_];
__device__ __nv_bfloat16 g_wqkv_hi[3 * D_ * D_];
__device__ __nv_bfloat16 g_wqkv_lo[3 * D_ * D_];
__device__ __nv_bfloat16 g_wout_hi[D_ * D_];
__device__ __nv_bfloat16 g_wout_lo[D_ * D_];
__device__ __nv_bfloat16 g_wf1_hi[F_ * D_];
__device__ __nv_bfloat16 g_wf1_lo[F_ * D_];
__device__ __nv_bfloat16 g_wf2_hi[D_ * F_];
__device__ __nv_bfloat16 g_wf2_lo[D_ * F_];

// ---------------------------------------------------------------------------
// Helpers
// ---------------------------------------------------------------------------
__device__ __forceinline__ uint32_t smem_u32(const void* p) {
    uint32_t a;
    asm("{ .reg .u64 t; cvta.to.shared.u64 t, %1; cvt.u32.u64 %0, t; }" : "=r"(a) : "l"(p));
    return a;
}

#define MMA_BF16(d, a, b) \
    asm volatile("mma.sync.aligned.m16n8k16.row.col.f32.bf16.bf16.f32 " \
        "{%0,%1,%2,%3}, {%4,%5,%6,%7}, {%8,%9}, {%0,%1,%2,%3};" \
        : "+f"((d)[0]), "+f"((d)[1]), "+f"((d)[2]), "+f"((d)[3]) \
        : "r"((a)[0]), "r"((a)[1]), "r"((a)[2]), "r"((a)[3]), "r"((b)[0]), "r"((b)[1]))

#define LDSM_X4(r, addr) \
    asm volatile("ldmatrix.sync.aligned.m8n8.x4.shared.b16 {%0,%1,%2,%3}, [%4];" \
        : "=r"((r)[0]), "=r"((r)[1]), "=r"((r)[2]), "=r"((r)[3]) : "r"(addr))

#define LDSM_X2(r, addr) \
    asm volatile("ldmatrix.sync.aligned.m8n8.x2.shared.b16 {%0,%1}, [%2];" \
        : "=r"((r)[0]), "=r"((r)[1]) : "r"(addr))

#define CP_ASYNC16(dst, src) \
    asm volatile("cp.async.cg.shared.global [%0], [%1], 16;" :: "r"(dst), "l"(src))
#define CP_COMMIT() asm volatile("cp.async.commit_group;" ::: "memory")
#define CP_WAIT(n)  asm volatile("cp.async.wait_group %0;" :: "n"(n) : "memory")

// ---------------------------------------------------------------------------
// Split-bf16 tensor-core GEMM: C[M,N] = A[M,K] @ W[N,K]^T + bias (opt ReLU)
// 128x128 CTA tile, 256 threads (8 warps, 64x32 warp tile), BK=32,
// double-buffered cp.async. A,W as (hi,lo) bf16; C fp32 and/or (hi,lo) bf16.
// ---------------------------------------------------------------------------
#define LDA 40                       // smem row stride in bf16 (80 B)
#define MATB (128 * LDA * 2)         // 10240 B per matrix tile
#define BUFB (4 * MATB)              // 40960 B per pipeline buffer
#define GEMM_SMEM (2 * BUFB)         // 81920 B (stage 128x132 f32 = 67584 fits)

__device__ __forceinline__ void gemm_issue(
    const __nv_bfloat16* __restrict__ Ahi, const __nv_bfloat16* __restrict__ Alo,
    const __nv_bfloat16* __restrict__ Bhi, const __nv_bfloat16* __restrict__ Blo,
    uint32_t sbuf, int bm0, int bn0, int kt, int K, int tid)
{
#pragma unroll
    for (int q = 0; q < 2; q++) {
        int e   = tid + (q << 8);        // 0..511
        int row = e >> 2;                // 0..127
        int c   = (e & 3) << 3;          // 0,8,16,24 (bf16 elems)
        uint32_t so = (uint32_t)(row * LDA + c) * 2;
        size_t ga = (size_t)(bm0 + row) * K + kt + c;
        size_t gb = (size_t)(bn0 + row) * K + kt + c;
        CP_ASYNC16(sbuf + 0 * MATB + so, (const void*)(Ahi + ga));
        CP_ASYNC16(sbuf + 1 * MATB + so, (const void*)(Alo + ga));
        CP_ASYNC16(sbuf + 2 * MATB + so, (const void*)(Bhi + gb));
        CP_ASYNC16(sbuf + 3 * MATB + so, (const void*)(Blo + gb));
    }
}

__global__ __launch_bounds__(256, 1)
void gemm_mma(const __nv_bfloat16* __restrict__ Ahi, const __nv_bfloat16* __restrict__ Alo,
              const __nv_bfloat16* __restrict__ Bhi, const __nv_bfloat16* __restrict__ Blo,
              const float* __restrict__ bias,
              float* __restrict__ Cf, __nv_bfloat16* __restrict__ Chi,
              __nv_bfloat16* __restrict__ Clo,
              int M, int N, int K, int relu)
{
    extern __shared__ __align__(128) char smraw[];
    uint32_t sb = smem_u32(smraw);

    const int tid  = threadIdx.x;
    const int wid  = tid >> 5;
    const int lane = tid & 31;
    const int bm0  = blockIdx.y * 128;
    const int bn0  = blockIdx.x * 128;
    const int m_warp = (wid >> 2) * 64;     // 0 or 64
    const int n_warp = (wid & 3) * 32;      // 0,32,64,96
    const int arow  = lane & 15;
    const int acol8 = (lane >> 4) << 3;
    const int brow  = lane & 7;
    const int bcol8 = ((lane >> 3) & 1) << 3;

    float d[16][4];
#pragma unroll
    for (int i = 0; i < 16; i++)
#pragma unroll
        for (int j = 0; j < 4; j++) d[i][j] = 0.f;

    const int KIT = K >> 5;
    gemm_issue(Ahi, Alo, Bhi, Blo, sb, bm0, bn0, 0, K, tid);
    CP_COMMIT();

    int buf = 0;
    for (int it = 0; it < KIT; it++) {
        if (it + 1 < KIT) {
            gemm_issue(Ahi, Alo, Bhi, Blo, sb + (buf ^ 1) * BUFB, bm0, bn0,
                       (it + 1) << 5, K, tid);
            CP_COMMIT();
            CP_WAIT(1);
        } else {
            CP_WAIT(0);
        }
        __syncthreads();

        uint32_t base = sb + buf * BUFB;
#pragma unroll
        for (int ks = 0; ks < 2; ks++) {
            uint32_t Ah[4][4], Al[4][4], Bh[4][2], Bl[4][2];
#pragma unroll
            for (int im = 0; im < 4; im++) {
                uint32_t ra = base + (uint32_t)((m_warp + im * 16 + arow) * LDA
                                                + ks * 16 + acol8) * 2;
                LDSM_X4(Ah[im], ra);
                LDSM_X4(Al[im], ra + MATB);
            }
#pragma unroll
            for (int in = 0; in < 4; in++) {
                uint32_t rb = base + 2 * MATB
                            + (uint32_t)((n_warp + in * 8 + brow) * LDA
                                         + ks * 16 + bcol8) * 2;
                LDSM_X2(Bh[in], rb);
                LDSM_X2(Bl[in], rb + MATB);
            }
#pragma unroll
            for (int im = 0; im < 4; im++)
#pragma unroll
                for (int in = 0; in < 4; in++) {
                    MMA_BF16(d[im * 4 + in], Ah[im], Bh[in]);
                    MMA_BF16(d[im * 4 + in], Ah[im], Bl[in]);
                    MMA_BF16(d[im * 4 + in], Al[im], Bh[in]);
                }
        }
        __syncthreads();
        buf ^= 1;
    }

    // Epilogue: accum -> smem stage -> coalesced gmem, fused bias/ReLU/split.
    float* stage = (float*)smraw;            // 128 x 132
#pragma unroll
    for (int im = 0; im < 4; im++)
#pragma unroll
        for (int in = 0; in < 4; in++) {
            float* dd = d[im * 4 + in];
            int row = m_warp + im * 16 + (lane >> 2);
            int col = n_warp + in * 8 + (lane & 3) * 2;
            *(float2*)&stage[row * 132 + col]       = make_float2(dd[0], dd[1]);
            *(float2*)&stage[(row + 8) * 132 + col] = make_float2(dd[2], dd[3]);
        }
    __syncthreads();

    const int erow = tid >> 1;
    const int ec0  = (tid & 1) << 6;         // 0 or 64
    size_t gbase = (size_t)(bm0 + erow) * N + bn0 + ec0;
#pragma unroll 4
    for (int c = 0; c < 64; c += 4) {
        float v[4];
#pragma unroll
        for (int k = 0; k < 4; k++) {
            float x = stage[erow * 132 + ec0 + c + k] + __ldg(&bias[bn0 + ec0 + c + k]);
            if (relu) x = fmaxf(x, 0.f);
            v[k] = x;
        }
        if (Cf)
            *(float4*)(Cf + gbase + c) = make_float4(v[0], v[1], v[2], v[3]);
        if (Chi) {
            __nv_bfloat16 h0 = __float2bfloat16(v[0]), h1 = __float2bfloat16(v[1]);
            __nv_bfloat16 h2 = __float2bfloat16(v[2]), h3 = __float2bfloat16(v[3]);
            *(__nv_bfloat162*)(Chi + gbase + c)     = __halves2bfloat162(h0, h1);
            *(__nv_bfloat162*)(Chi + gbase + c + 2) = __halves2bfloat162(h2, h3);
            *(__nv_bfloat162*)(Clo + gbase + c)     = __halves2bfloat162(
                __float2bfloat16(v[0] - __bfloat162float(h0)),
                __float2bfloat16(v[1] - __bfloat162float(h1)));
            *(__nv_bfloat162*)(Clo + gbase + c + 2) = __halves2bfloat162(
                __float2bfloat16(v[2] - __bfloat162float(h2)),
                __float2bfloat16(v[3] - __bfloat162float(h3)));
        }
    }
}

// ---------------------------------------------------------------------------
// fp32 -> (hi, lo) bf16 split
// ---------------------------------------------------------------------------
__global__ void split_bf16_kernel(const float* __restrict__ x,
                                  __nv_bfloat16* __restrict__ hi,
                                  __nv_bfloat16* __restrict__ lo, int n4) {
    int i = blockIdx.x * blockDim.x + threadIdx.x;
    if (i >= n4) return;
    float4 v = ((const float4*)x)[i];
    __nv_bfloat16 h0 = __float2bfloat16(v.x);
    __nv_bfloat16 h1 = __float2bfloat16(v.y);
    __nv_bfloat16 h2 = __float2bfloat16(v.z);
    __nv_bfloat16 h3 = __float2bfloat16(v.w);
    ((__nv_bfloat162*)hi)[2 * i]     = __halves2bfloat162(h0, h1);
    ((__nv_bfloat162*)hi)[2 * i + 1] = __halves2bfloat162(h2, h3);
    ((__nv_bfloat162*)lo)[2 * i]     = __halves2bfloat162(
        __float2bfloat16(v.x - __bfloat162float(h0)),
        __float2bfloat16(v.y - __bfloat162float(h1)));
    ((__nv_bfloat162*)lo)[2 * i + 1] = __halves2bfloat162(
        __float2bfloat16(v.z - __bfloat162float(h2)),
        __float2bfloat16(v.w - __bfloat162float(h3)));
}

// ---------------------------------------------------------------------------
// Flash attention, fp32; epilogue emits ctx as (hi,lo) bf16.
// ---------------------------------------------------------------------------
#define FSTR 65
#define FLASH_SMEM (4 * 64 * FSTR * 4)

__global__ __launch_bounds__(256)
void flash_kernel(const float* __restrict__ qkv,
                  __nv_bfloat16* __restrict__ ctx_hi,
                  __nv_bfloat16* __restrict__ ctx_lo) {
    extern __shared__ float sm[];
    float* Qs = sm;
    float* Ks = Qs + 64 * FSTR;
    float* Vs = Ks + 64 * FSTR;
    float* Ps = Vs + 64 * FSTR;

    const int tid = threadIdx.x;
    const int bh  = blockIdx.y;
    const int b   = bh / H_;
    const int h   = bh % H_;
    const float* base = qkv + (size_t)b * S_ * (3 * D_) + h * (3 * HD_);
    const int q0 = blockIdx.x * 64;

#pragma unroll
    for (int it = 0; it < 4; it++) {
        int e   = tid + 256 * it;
        int row = e >> 4;
        int c   = (e & 15) * 4;
        float4 v = *(const float4*)(base + (size_t)(q0 + row) * (3 * D_) + c);
        Qs[row * FSTR + c + 0] = v.x * 0.125f;
        Qs[row * FSTR + c + 1] = v.y * 0.125f;
        Qs[row * FSTR + c + 2] = v.z * 0.125f;
        Qs[row * FSTR + c + 3] = v.w * 0.125f;
    }

    const int r0 = (tid >> 4) * 4;
    const int c0 = (tid & 15) * 4;

    float m[4], l[4], acc[4][4];
#pragma unroll
    for (int i = 0; i < 4; i++) {
        m[i] = -INFINITY; l[i] = 0.f;
#pragma unroll
        for (int j = 0; j < 4; j++) acc[i][j] = 0.f;
    }

    for (int kt = 0; kt < S_; kt += 64) {
        __syncthreads();
#pragma unroll
        for (int it = 0; it < 4; it++) {
            int e   = tid + 256 * it;
            int row = e >> 4;
            int c   = (e & 15) * 4;
            const float* kp = base + (size_t)(kt + row) * (3 * D_) + HD_ + c;
            float4 kv = *(const float4*)kp;
            Ks[row * FSTR + c + 0] = kv.x;
            Ks[row * FSTR + c + 1] = kv.y;
            Ks[row * FSTR + c + 2] = kv.z;
            Ks[row * FSTR + c + 3] = kv.w;
            float4 vv = *(const float4*)(kp + HD_);
            Vs[row * FSTR + c + 0] = vv.x;
            Vs[row * FSTR + c + 1] = vv.y;
            Vs[row * FSTR + c + 2] = vv.z;
            Vs[row * FSTR + c + 3] = vv.w;
        }
        __syncthreads();

        float s[4][4];
#pragma unroll
        for (int i = 0; i < 4; i++)
#pragma unroll
            for (int j = 0; j < 4; j++) s[i][j] = 0.f;

#pragma unroll 4
        for (int dd = 0; dd < 64; dd++) {
            float q_[4], k_[4];
#pragma unroll
            for (int i = 0; i < 4; i++) q_[i] = Qs[(r0 + i) * FSTR + dd];
#pragma unroll
            for (int j = 0; j < 4; j++) k_[j] = Ks[(c0 + j) * FSTR + dd];
#pragma unroll
            for (int i = 0; i < 4; i++)
#pragma unroll
                for (int j = 0; j < 4; j++)
                    s[i][j] = fmaf(q_[i], k_[j], s[i][j]);
        }

#pragma unroll
        for (int i = 0; i < 4; i++) {
            float tm = fmaxf(fmaxf(s[i][0], s[i][1]), fmaxf(s[i][2], s[i][3]));
#pragma unroll
            for (int off = 8; off >= 1; off >>= 1)
                tm = fmaxf(tm, __shfl_xor_sync(0xffffffffu, tm, off));
            float mnew  = fmaxf(m[i], tm);
            float alpha = __expf(m[i] - mnew);
            float psum  = 0.f;
#pragma unroll
            for (int j = 0; j < 4; j++) {
                float p = __expf(s[i][j] - mnew);
                Ps[(r0 + i) * FSTR + c0 + j] = p;
                psum += p;
            }
#pragma unroll
            for (int off = 8; off >= 1; off >>= 1)
                psum += __shfl_xor_sync(0xffffffffu, psum, off);
            l[i] = l[i] * alpha + psum;
            m[i] = mnew;
#pragma unroll
            for (int dd = 0; dd < 4; dd++) acc[i][dd] *= alpha;
        }
        __syncthreads();

#pragma unroll 4
        for (int j = 0; j < 64; j++) {
            float v_[4], p_[4];
#pragma unroll
            for (int dd = 0; dd < 4; dd++) v_[dd] = Vs[j * FSTR + c0 + dd];
#pragma unroll
            for (int i = 0; i < 4; i++)  p_[i]  = Ps[(r0 + i) * FSTR + j];
#pragma unroll
            for (int i = 0; i < 4; i++)
#pragma unroll
                for (int dd = 0; dd < 4; dd++)
                    acc[i][dd] = fmaf(p_[i], v_[dd], acc[i][dd]);
        }
    }

    __nv_bfloat16* oph = ctx_hi + ((size_t)(b * S_) + q0) * D_ + h * HD_;
    __nv_bfloat16* opl = ctx_lo + ((size_t)(b * S_) + q0) * D_ + h * HD_;
#pragma unroll
    for (int i = 0; i < 4; i++) {
        float inv = 1.f / l[i];
        float v0 = acc[i][0] * inv, v1 = acc[i][1] * inv;
        float v2 = acc[i][2] * inv, v3 = acc[i][3] * inv;
        __nv_bfloat16 h0 = __float2bfloat16(v0), h1 = __float2bfloat16(v1);
        __nv_bfloat16 h2 = __float2bfloat16(v2), h3 = __float2bfloat16(v3);
        size_t o = (size_t)(r0 + i) * D_ + c0;
        *(__nv_bfloat162*)&oph[o]     = __halves2bfloat162(h0, h1);
        *(__nv_bfloat162*)&oph[o + 2] = __halves2bfloat162(h2, h3);
        *(__nv_bfloat162*)&opl[o]     = __halves2bfloat162(
            __float2bfloat16(v0 - __bfloat162float(h0)),
            __float2bfloat16(v1 - __bfloat162float(h1)));
        *(__nv_bfloat162*)&opl[o + 2] = __halves2bfloat162(
            __float2bfloat16(v2 - __bfloat162float(h2)),
            __float2bfloat16(v3 - __bfloat162float(h3)));
    }
}

// ---------------------------------------------------------------------------
// Fused residual + LayerNorm (+ optional hi/lo bf16 emit)
// ---------------------------------------------------------------------------
__global__ __launch_bounds__(256)
void add_ln_kernel(const float* __restrict__ x, const float* __restrict__ r,
                   const float* __restrict__ g, const float* __restrict__ bb,
                   float* __restrict__ out,
                   __nv_bfloat16* __restrict__ ohi, __nv_bfloat16* __restrict__ olo) {
    __shared__ float red[16];
    const int row = blockIdx.x;
    const int tid = threadIdx.x;

    float4 xv = ((const float4*)(x + (size_t)row * D_))[tid];
    float4 rv = ((const float4*)(r + (size_t)row * D_))[tid];
    float v0 = xv.x + rv.x, v1 = xv.y + rv.y, v2 = xv.z + rv.z, v3 = xv.w + rv.w;

    float s  = v0 + v1 + v2 + v3;
    float sq = v0 * v0 + v1 * v1 + v2 * v2 + v3 * v3;
#pragma unroll
    for (int o = 16; o >= 1; o >>= 1) {
        s  += __shfl_xor_sync(0xffffffffu, s,  o);
        sq += __shfl_xor_sync(0xffffffffu, sq, o);
    }
    int warp = tid >> 5, lane = tid & 31;
    if (lane == 0) { red[warp] = s; red[8 + warp] = sq; }
    __syncthreads();
    if (tid == 0) {
        float ts = 0.f, tq = 0.f;
#pragma unroll
        for (int i = 0; i < 8; i++) { ts += red[i]; tq += red[8 + i]; }
        float mean = ts * (1.0f / D_);
        float var  = tq * (1.0f / D_) - mean * mean;
        red[0] = mean;
        red[1] = rsqrtf(var + EPSLN);
    }
    __syncthreads();
    float mean = red[0], rstd = red[1];

    float4 gv = ((const float4*)g)[tid];
    float4 bv = ((const float4*)bb)[tid];
    float o0 = (v0 - mean) * rstd * gv.x + bv.x;
    float o1 = (v1 - mean) * rstd * gv.y + bv.y;
    float o2 = (v2 - mean) * rstd * gv.z + bv.z;
    float o3 = (v3 - mean) * rstd * gv.w + bv.w;
    ((float4*)(out + (size_t)row * D_))[tid] = make_float4(o0, o1, o2, o3);

    if (ohi) {
        __nv_bfloat16 h0 = __float2bfloat16(o0), h1 = __float2bfloat16(o1);
        __nv_bfloat16 h2 = __float2bfloat16(o2), h3 = __float2bfloat16(o3);
        size_t o = (size_t)row * D_ + tid * 4;
        *(__nv_bfloat162*)&ohi[o]     = __halves2bfloat162(h0, h1);
        *(__nv_bfloat162*)&ohi[o + 2] = __halves2bfloat162(h2, h3);
        *(__nv_bfloat162*)&olo[o]     = __halves2bfloat162(
            __float2bfloat16(o0 - __bfloat162float(h0)),
            __float2bfloat16(o1 - __bfloat162float(h1)));
        *(__nv_bfloat162*)&olo[o + 2] = __halves2bfloat162(
            __float2bfloat16(o2 - __bfloat162float(h2)),
            __float2bfloat16(o3 - __bfloat162float(h3)));
    }
}

// ---------------------------------------------------------------------------
// Host launcher
// ---------------------------------------------------------------------------
static inline void split_launch(const float* x, __nv_bfloat16* hi, __nv_bfloat16* lo, int n) {
    int n4 = n / 4;
    split_bf16_kernel<<<(n4 + 255) / 256, 256>>>(x, hi, lo, n4);
}

extern "C" void kernel_launch(void* const* d_in, const int* in_sizes, int n_in,
                              void* d_out, int out_size) {
    const float* src    = (const float*)d_in[0];
    const float* qkv_w  = (const float*)d_in[1];
    const float* qkv_b  = (const float*)d_in[2];
    const float* out_w  = (const float*)d_in[3];
    const float* out_b  = (const float*)d_in[4];
    const float* ffn_w1 = (const float*)d_in[5];
    const float* ffn_b1 = (const float*)d_in[6];
    const float* ffn_w2 = (const float*)d_in[7];
    const float* ffn_b2 = (const float*)d_in[8];
    const float* ln1_g  = (const float*)d_in[9];
    const float* ln1_b  = (const float*)d_in[10];
    const float* ln2_g  = (const float*)d_in[11];
    const float* ln2_b  = (const float*)d_in[12];
    float* out = (float*)d_out;

    float *qkv, *tmp, *agg;
    __nv_bfloat16 *src_hi, *src_lo, *ctx_hi, *ctx_lo, *agg_hi, *agg_lo, *h1_hi, *h1_lo;
    __nv_bfloat16 *wqkv_hi, *wqkv_lo, *wout_hi, *wout_lo, *wf1_hi, *wf1_lo, *wf2_hi, *wf2_lo;
    cudaGetSymbolAddress((void**)&qkv, g_qkv);
    cudaGetSymbolAddress((void**)&tmp, g_tmp);
    cudaGetSymbolAddress((void**)&agg, g_agg);
    cudaGetSymbolAddress((void**)&src_hi, g_src_hi);
    cudaGetSymbolAddress((void**)&src_lo, g_src_lo);
    cudaGetSymbolAddress((void**)&ctx_hi, g_ctx_hi);
    cudaGetSymbolAddress((void**)&ctx_lo, g_ctx_lo);
    cudaGetSymbolAddress((void**)&agg_hi, g_agg_hi);
    cudaGetSymbolAddress((void**)&agg_lo, g_agg_lo);
    cudaGetSymbolAddress((void**)&h1_hi, g_h1_hi);
    cudaGetSymbolAddress((void**)&h1_lo, g_h1_lo);
    cudaGetSymbolAddress((void**)&wqkv_hi, g_wqkv_hi);
    cudaGetSymbolAddress((void**)&wqkv_lo, g_wqkv_lo);
    cudaGetSymbolAddress((void**)&wout_hi, g_wout_hi);
    cudaGetSymbolAddress((void**)&wout_lo, g_wout_lo);
    cudaGetSymbolAddress((void**)&wf1_hi, g_wf1_hi);
    cudaGetSymbolAddress((void**)&wf1_lo, g_wf1_lo);
    cudaGetSymbolAddress((void**)&wf2_hi, g_wf2_hi);
    cudaGetSymbolAddress((void**)&wf2_lo, g_wf2_lo);

    cudaFuncSetAttribute(flash_kernel,
                         cudaFuncAttributeMaxDynamicSharedMemorySize, FLASH_SMEM);
    cudaFuncSetAttribute(gemm_mma,
                         cudaFuncAttributeMaxDynamicSharedMemorySize, GEMM_SMEM);

    // Split inputs to (hi, lo) bf16
    split_launch(src, src_hi, src_lo, NTOK * D_);
    split_launch(qkv_w, wqkv_hi, wqkv_lo, 3 * D_ * D_);
    split_launch(out_w, wout_hi, wout_lo, D_ * D_);
    split_launch(ffn_w1, wf1_hi, wf1_lo, F_ * D_);
    split_launch(ffn_w2, wf2_hi, wf2_lo, D_ * F_);

    // 1. QKV projection (fp32 out for flash)
    gemm_mma<<<dim3(3 * D_ / 128, NTOK / 128), 256, GEMM_SMEM>>>(
        src_hi, src_lo, wqkv_hi, wqkv_lo, qkv_b, qkv, nullptr, nullptr,
        NTOK, 3 * D_, D_, 0);

    // 2. Flash attention -> ctx (hi, lo)
    flash_kernel<<<dim3(S_ / 64, B_ * H_), 256, FLASH_SMEM>>>(qkv, ctx_hi, ctx_lo);

    // 3. Output projection -> tmp (mha_out fp32)
    gemm_mma<<<dim3(D_ / 128, NTOK / 128), 256, GEMM_SMEM>>>(
        ctx_hi, ctx_lo, wout_hi, wout_lo, out_b, tmp, nullptr, nullptr,
        NTOK, D_, D_, 0);

    // 4. agg = LN1(src + mha_out) (+ hi/lo)
    add_ln_kernel<<<NTOK, 256>>>(src, tmp, ln1_g, ln1_b, agg, agg_hi, agg_lo);

    // 5. FFN1 + ReLU -> h1 (hi/lo only)
    gemm_mma<<<dim3(F_ / 128, NTOK / 128), 256, GEMM_SMEM>>>(
        agg_hi, agg_lo, wf1_hi, wf1_lo, ffn_b1, nullptr, h1_hi, h1_lo,
        NTOK, F_, D_, 1);

    // 6. FFN2 -> tmp (ffn_out fp32)
    gemm_mma<<<dim3(D_ / 128, NTOK / 128), 256, GEMM_SMEM>>>(
        h1_hi, h1_lo, wf2_hi, wf2_lo, ffn_b2, tmp, nullptr, nullptr,
        NTOK, D_, F_, 0);

    // 7. out = LN2(agg + ffn_out)
    add_ln_kernel<<<NTOK, 256>>>(agg, tmp, ln2_g, ln2_b, out, nullptr, nullptr);
}

// round 6
// speedup vs baseline: 2.6438x; 1.7454x over previous
#include <cuda_runtime.h>
#include <cuda_bf16.h>
#include <math.h>
#include <stdint.h>

// Problem constants
#define B_   2
#define S_   2048
#define D_   1024
#define H_   16
#define HD_  64
#define F_   4096
#define NTOK (B_ * S_)
#define EPSLN 1e-5f

// ---------------------------------------------------------------------------
// Scratch (device globals)
// ---------------------------------------------------------------------------
__device__ float g_tmp[NTOK * D_];
__device__ float g_agg[NTOK * D_];
__device__ __nv_bfloat16 g_qkvh[NTOK * 3 * D_];
__device__ __nv_bfloat16 g_src_hi[NTOK * D_];
__device__ __nv_bfloat16 g_src_lo[NTOK * D_];
__device__ __nv_bfloat16 g_ctx_hi[NTOK * D_];
__device__ __nv_bfloat16 g_ctx_lo[NTOK * D_];
__device__ __nv_bfloat16 g_agg_hi[NTOK * D_];
__device__ __nv_bfloat16 g_agg_lo[NTOK * D_];
__device__ __nv_bfloat16 g_h1_hi[NTOK * F_];
__device__ __nv_bfloat16 g_h1_lo[NTOK * F_];
__device__ __nv_bfloat16 g_wqkv_hi[3 * D_ * D_];
__device__ __nv_bfloat16 g_wqkv_lo[3 * D_ * D_];
__device__ __nv_bfloat16 g_wout_hi[D_ * D_];
__device__ __nv_bfloat16 g_wout_lo[D_ * D_];
__device__ __nv_bfloat16 g_wf1_hi[F_ * D_];
__device__ __nv_bfloat16 g_wf1_lo[F_ * D_];
__device__ __nv_bfloat16 g_wf2_hi[D_ * F_];
__device__ __nv_bfloat16 g_wf2_lo[D_ * F_];

// ---------------------------------------------------------------------------
// Helpers
// ---------------------------------------------------------------------------
__device__ __forceinline__ uint32_t smem_u32(const void* p) {
    uint32_t a;
    asm("{ .reg .u64 t; cvta.to.shared.u64 t, %1; cvt.u32.u64 %0, t; }" : "=r"(a) : "l"(p));
    return a;
}

#define MMA_BF16(d, a, b) \
    asm volatile("mma.sync.aligned.m16n8k16.row.col.f32.bf16.bf16.f32 " \
        "{%0,%1,%2,%3}, {%4,%5,%6,%7}, {%8,%9}, {%0,%1,%2,%3};" \
        : "+f"((d)[0]), "+f"((d)[1]), "+f"((d)[2]), "+f"((d)[3]) \
        : "r"((a)[0]), "r"((a)[1]), "r"((a)[2]), "r"((a)[3]), "r"((b)[0]), "r"((b)[1]))

#define LDSM_X4(r, addr) \
    asm volatile("ldmatrix.sync.aligned.m8n8.x4.shared.b16 {%0,%1,%2,%3}, [%4];" \
        : "=r"((r)[0]), "=r"((r)[1]), "=r"((r)[2]), "=r"((r)[3]) : "r"(addr))

#define LDSM_X4_T(r, addr) \
    asm volatile("ldmatrix.sync.aligned.m8n8.x4.trans.shared.b16 {%0,%1,%2,%3}, [%4];" \
        : "=r"((r)[0]), "=r"((r)[1]), "=r"((r)[2]), "=r"((r)[3]) : "r"(addr))

#define LDSM_X2(r, addr) \
    asm volatile("ldmatrix.sync.aligned.m8n8.x2.shared.b16 {%0,%1}, [%2];" \
        : "=r"((r)[0]), "=r"((r)[1]) : "r"(addr))

#define CP_ASYNC16(dst, src) \
    asm volatile("cp.async.cg.shared.global [%0], [%1], 16;" :: "r"(dst), "l"(src))
#define CP_COMMIT() asm volatile("cp.async.commit_group;" ::: "memory")
#define CP_WAIT(n)  asm volatile("cp.async.wait_group %0;" :: "n"(n) : "memory")

// ---------------------------------------------------------------------------
// Split-bf16 tensor-core GEMM (unchanged mainloop from R5; lo-write optional)
// ---------------------------------------------------------------------------
#define LDA 40
#define MATB (128 * LDA * 2)
#define BUFB (4 * MATB)
#define GEMM_SMEM (2 * BUFB)

__device__ __forceinline__ void gemm_issue(
    const __nv_bfloat16* __restrict__ Ahi, const __nv_bfloat16* __restrict__ Alo,
    const __nv_bfloat16* __restrict__ Bhi, const __nv_bfloat16* __restrict__ Blo,
    uint32_t sbuf, int bm0, int bn0, int kt, int K, int tid)
{
#pragma unroll
    for (int q = 0; q < 2; q++) {
        int e   = tid + (q << 8);
        int row = e >> 2;
        int c   = (e & 3) << 3;
        uint32_t so = (uint32_t)(row * LDA + c) * 2;
        size_t ga = (size_t)(bm0 + row) * K + kt + c;
        size_t gb = (size_t)(bn0 + row) * K + kt + c;
        CP_ASYNC16(sbuf + 0 * MATB + so, (const void*)(Ahi + ga));
        CP_ASYNC16(sbuf + 1 * MATB + so, (const void*)(Alo + ga));
        CP_ASYNC16(sbuf + 2 * MATB + so, (const void*)(Bhi + gb));
        CP_ASYNC16(sbuf + 3 * MATB + so, (const void*)(Blo + gb));
    }
}

__global__ __launch_bounds__(256, 1)
void gemm_mma(const __nv_bfloat16* __restrict__ Ahi, const __nv_bfloat16* __restrict__ Alo,
              const __nv_bfloat16* __restrict__ Bhi, const __nv_bfloat16* __restrict__ Blo,
              const float* __restrict__ bias,
              float* __restrict__ Cf, __nv_bfloat16* __restrict__ Chi,
              __nv_bfloat16* __restrict__ Clo,
              int M, int N, int K, int relu)
{
    extern __shared__ __align__(128) char smraw[];
    uint32_t sb = smem_u32(smraw);

    const int tid  = threadIdx.x;
    const int wid  = tid >> 5;
    const int lane = tid & 31;
    const int bm0  = blockIdx.y * 128;
    const int bn0  = blockIdx.x * 128;
    const int m_warp = (wid >> 2) * 64;
    const int n_warp = (wid & 3) * 32;
    const int arow  = lane & 15;
    const int acol8 = (lane >> 4) << 3;
    const int brow  = lane & 7;
    const int bcol8 = ((lane >> 3) & 1) << 3;

    float d[16][4];
#pragma unroll
    for (int i = 0; i < 16; i++)
#pragma unroll
        for (int j = 0; j < 4; j++) d[i][j] = 0.f;

    const int KIT = K >> 5;
    gemm_issue(Ahi, Alo, Bhi, Blo, sb, bm0, bn0, 0, K, tid);
    CP_COMMIT();

    int buf = 0;
    for (int it = 0; it < KIT; it++) {
        if (it + 1 < KIT) {
            gemm_issue(Ahi, Alo, Bhi, Blo, sb + (buf ^ 1) * BUFB, bm0, bn0,
                       (it + 1) << 5, K, tid);
            CP_COMMIT();
            CP_WAIT(1);
        } else {
            CP_WAIT(0);
        }
        __syncthreads();

        uint32_t base = sb + buf * BUFB;
#pragma unroll
        for (int ks = 0; ks < 2; ks++) {
            uint32_t Ah[4][4], Al[4][4], Bh[4][2], Bl[4][2];
#pragma unroll
            for (int im = 0; im < 4; im++) {
                uint32_t ra = base + (uint32_t)((m_warp + im * 16 + arow) * LDA
                                                + ks * 16 + acol8) * 2;
                LDSM_X4(Ah[im], ra);
                LDSM_X4(Al[im], ra + MATB);
            }
#pragma unroll
            for (int in = 0; in < 4; in++) {
                uint32_t rb = base + 2 * MATB
                            + (uint32_t)((n_warp + in * 8 + brow) * LDA
                                         + ks * 16 + bcol8) * 2;
                LDSM_X2(Bh[in], rb);
                LDSM_X2(Bl[in], rb + MATB);
            }
#pragma unroll
            for (int im = 0; im < 4; im++)
#pragma unroll
                for (int in = 0; in < 4; in++) {
                    MMA_BF16(d[im * 4 + in], Ah[im], Bh[in]);
                    MMA_BF16(d[im * 4 + in], Ah[im], Bl[in]);
                    MMA_BF16(d[im * 4 + in], Al[im], Bh[in]);
                }
        }
        __syncthreads();
        buf ^= 1;
    }

    float* stage = (float*)smraw;
#pragma unroll
    for (int im = 0; im < 4; im++)
#pragma unroll
        for (int in = 0; in < 4; in++) {
            float* dd = d[im * 4 + in];
            int row = m_warp + im * 16 + (lane >> 2);
            int col = n_warp + in * 8 + (lane & 3) * 2;
            *(float2*)&stage[row * 132 + col]       = make_float2(dd[0], dd[1]);
            *(float2*)&stage[(row + 8) * 132 + col] = make_float2(dd[2], dd[3]);
        }
    __syncthreads();

    const int erow = tid >> 1;
    const int ec0  = (tid & 1) << 6;
    size_t gbase = (size_t)(bm0 + erow) * N + bn0 + ec0;
#pragma unroll 4
    for (int c = 0; c < 64; c += 4) {
        float v[4];
#pragma unroll
        for (int k = 0; k < 4; k++) {
            float x = stage[erow * 132 + ec0 + c + k] + __ldg(&bias[bn0 + ec0 + c + k]);
            if (relu) x = fmaxf(x, 0.f);
            v[k] = x;
        }
        if (Cf)
            *(float4*)(Cf + gbase + c) = make_float4(v[0], v[1], v[2], v[3]);
        if (Chi) {
            __nv_bfloat16 h0 = __float2bfloat16(v[0]), h1 = __float2bfloat16(v[1]);
            __nv_bfloat16 h2 = __float2bfloat16(v[2]), h3 = __float2bfloat16(v[3]);
            *(__nv_bfloat162*)(Chi + gbase + c)     = __halves2bfloat162(h0, h1);
            *(__nv_bfloat162*)(Chi + gbase + c + 2) = __halves2bfloat162(h2, h3);
            if (Clo) {
                *(__nv_bfloat162*)(Clo + gbase + c)     = __halves2bfloat162(
                    __float2bfloat16(v[0] - __bfloat162float(h0)),
                    __float2bfloat16(v[1] - __bfloat162float(h1)));
                *(__nv_bfloat162*)(Clo + gbase + c + 2) = __halves2bfloat162(
                    __float2bfloat16(v[2] - __bfloat162float(h2)),
                    __float2bfloat16(v[3] - __bfloat162float(h3)));
            }
        }
    }
}

// ---------------------------------------------------------------------------
// fp32 -> (hi, lo) bf16 split
// ---------------------------------------------------------------------------
__global__ void split_bf16_kernel(const float* __restrict__ x,
                                  __nv_bfloat16* __restrict__ hi,
                                  __nv_bfloat16* __restrict__ lo, int n4) {
    int i = blockIdx.x * blockDim.x + threadIdx.x;
    if (i >= n4) return;
    float4 v = ((const float4*)x)[i];
    __nv_bfloat16 h0 = __float2bfloat16(v.x);
    __nv_bfloat16 h1 = __float2bfloat16(v.y);
    __nv_bfloat16 h2 = __float2bfloat16(v.z);
    __nv_bfloat16 h3 = __float2bfloat16(v.w);
    ((__nv_bfloat162*)hi)[2 * i]     = __halves2bfloat162(h0, h1);
    ((__nv_bfloat162*)hi)[2 * i + 1] = __halves2bfloat162(h2, h3);
    ((__nv_bfloat162*)lo)[2 * i]     = __halves2bfloat162(
        __float2bfloat16(v.x - __bfloat162float(h0)),
        __float2bfloat16(v.y - __bfloat162float(h1)));
    ((__nv_bfloat162*)lo)[2 * i + 1] = __halves2bfloat162(
        __float2bfloat16(v.z - __bfloat162float(h2)),
        __float2bfloat16(v.w - __bfloat162float(h3)));
}

// ---------------------------------------------------------------------------
// Tensor-core flash attention (bf16 HMMA, fp32 softmax/accum)
// CTA: 128 q-rows of one (b,h); 8 warps x 16 q-rows. Key tiles of 64.
// qkv bf16 layout per token row: head h at col h*192: [q64 | k64 | v64].
// ---------------------------------------------------------------------------
#define LQ 72                               // smem row stride (bf16)
#define FQ_ELEMS (128 * LQ)                 // 9216
#define FK_ELEMS (64 * LQ)                  // 4608
#define FLASH_SMEM ((FQ_ELEMS + 4 * FK_ELEMS) * 2)   // 55296 B

__global__ __launch_bounds__(256, 2)
void flash_mma(const __nv_bfloat16* __restrict__ qkv,
               __nv_bfloat16* __restrict__ ctx_hi,
               __nv_bfloat16* __restrict__ ctx_lo) {
    extern __shared__ __align__(128) __nv_bfloat16 fsm[];
    const uint32_t sQ = smem_u32(fsm);
    const uint32_t sK0 = sQ + FQ_ELEMS * 2;         // byte offsets
    const uint32_t sV0 = sK0 + FK_ELEMS * 2;
    const uint32_t sK1 = sV0 + FK_ELEMS * 2;
    const uint32_t sV1 = sK1 + FK_ELEMS * 2;

    const int tid  = threadIdx.x;
    const int wid  = tid >> 5;
    const int lane = tid & 31;
    const int bh   = blockIdx.y;
    const int b    = bh >> 4;
    const int h    = bh & 15;
    const int q0   = blockIdx.x * 128;
    const int wq0  = wid * 16;

    const __nv_bfloat16* base = qkv + (size_t)b * S_ * (3 * D_) + h * (3 * HD_);

    // --- initial async loads: Q tile + K/V tile 0 (group 0) ---
#pragma unroll
    for (int q = 0; q < 4; q++) {
        int c   = tid + (q << 8);            // 0..1023
        int row = c >> 3;
        int ch  = (c & 7) << 3;              // bf16 offset
        CP_ASYNC16(sQ + (uint32_t)(row * LQ + ch) * 2,
                   (const void*)(base + (size_t)(q0 + row) * (3 * D_) + ch));
    }
#pragma unroll
    for (int q = 0; q < 2; q++) {
        int c   = tid + (q << 8);            // 0..511
        int row = c >> 3;
        int ch  = (c & 7) << 3;
        const __nv_bfloat16* kp = base + (size_t)row * (3 * D_) + HD_ + ch;
        CP_ASYNC16(sK0 + (uint32_t)(row * LQ + ch) * 2, (const void*)kp);
        CP_ASYNC16(sV0 + (uint32_t)(row * LQ + ch) * 2, (const void*)(kp + HD_));
    }
    CP_COMMIT();

    uint32_t qa[4][4];
    float o[8][4];
#pragma unroll
    for (int j = 0; j < 8; j++)
#pragma unroll
        for (int i = 0; i < 4; i++) o[j][i] = 0.f;
    float mA = -INFINITY, mB = -INFINITY, lA = 0.f, lB = 0.f;

    int buf = 0;
    for (int it = 0; it < S_ / 64; it++) {
        if (it + 1 < S_ / 64) {
            int kt = (it + 1) << 6;
            uint32_t dK = buf ? sK0 : sK1;
            uint32_t dV = buf ? sV0 : sV1;
#pragma unroll
            for (int q = 0; q < 2; q++) {
                int c   = tid + (q << 8);
                int row = c >> 3;
                int ch  = (c & 7) << 3;
                const __nv_bfloat16* kp = base + (size_t)(kt + row) * (3 * D_) + HD_ + ch;
                CP_ASYNC16(dK + (uint32_t)(row * LQ + ch) * 2, (const void*)kp);
                CP_ASYNC16(dV + (uint32_t)(row * LQ + ch) * 2, (const void*)(kp + HD_));
            }
            CP_COMMIT();
            CP_WAIT(1);
        } else {
            CP_WAIT(0);
        }
        __syncthreads();

        if (it == 0) {
            // Q fragments (persist in registers)
#pragma unroll
            for (int ks = 0; ks < 4; ks++) {
                uint32_t ra = sQ + (uint32_t)((wq0 + (lane & 15)) * LQ
                                              + ks * 16 + ((lane >> 4) << 3)) * 2;
                LDSM_X4(qa[ks], ra);
            }
        }
        const uint32_t cK = buf ? sK1 : sK0;
        const uint32_t cV = buf ? sV1 : sV0;

        // ---- S = Q @ K^T ----
        float s[8][4];
#pragma unroll
        for (int j = 0; j < 8; j++)
#pragma unroll
            for (int i = 0; i < 4; i++) s[j][i] = 0.f;

#pragma unroll
        for (int jp = 0; jp < 4; jp++)
#pragma unroll
            for (int ks = 0; ks < 4; ks++) {
                uint32_t kb[4];
                uint32_t rb = cK + (uint32_t)((jp * 16 + ((lane >> 4) << 3) + (lane & 7)) * LQ
                                              + ks * 16 + (((lane >> 3) & 1) << 3)) * 2;
                LDSM_X4(kb, rb);
                MMA_BF16(s[2 * jp],     qa[ks], kb + 0);
                MMA_BF16(s[2 * jp + 1], qa[ks], kb + 2);
            }

        // ---- online softmax (scale 1/8) ----
#pragma unroll
        for (int j = 0; j < 8; j++)
#pragma unroll
            for (int i = 0; i < 4; i++) s[j][i] *= 0.125f;

        float hA = -INFINITY, hB = -INFINITY;
#pragma unroll
        for (int j = 0; j < 8; j++) {
            hA = fmaxf(hA, fmaxf(s[j][0], s[j][1]));
            hB = fmaxf(hB, fmaxf(s[j][2], s[j][3]));
        }
        hA = fmaxf(hA, __shfl_xor_sync(0xffffffffu, hA, 1));
        hA = fmaxf(hA, __shfl_xor_sync(0xffffffffu, hA, 2));
        hB = fmaxf(hB, __shfl_xor_sync(0xffffffffu, hB, 1));
        hB = fmaxf(hB, __shfl_xor_sync(0xffffffffu, hB, 2));
        float mAn = fmaxf(mA, hA), mBn = fmaxf(mB, hB);
        float aA = __expf(mA - mAn), aB = __expf(mB - mBn);
        float sumA = 0.f, sumB = 0.f;
#pragma unroll
        for (int j = 0; j < 8; j++) {
            s[j][0] = __expf(s[j][0] - mAn);
            s[j][1] = __expf(s[j][1] - mAn);
            s[j][2] = __expf(s[j][2] - mBn);
            s[j][3] = __expf(s[j][3] - mBn);
            sumA += s[j][0] + s[j][1];
            sumB += s[j][2] + s[j][3];
        }
        sumA += __shfl_xor_sync(0xffffffffu, sumA, 1);
        sumA += __shfl_xor_sync(0xffffffffu, sumA, 2);
        sumB += __shfl_xor_sync(0xffffffffu, sumB, 1);
        sumB += __shfl_xor_sync(0xffffffffu, sumB, 2);
        lA = lA * aA + sumA;
        lB = lB * aB + sumB;
        mA = mAn; mB = mBn;
#pragma unroll
        for (int j = 0; j < 8; j++) {
            o[j][0] *= aA; o[j][1] *= aA;
            o[j][2] *= aB; o[j][3] *= aB;
        }

        // ---- O += P @ V ----
#pragma unroll
        for (int ks = 0; ks < 4; ks++) {
            uint32_t pa[4];
            __nv_bfloat162 t;
            t = __float22bfloat162_rn(make_float2(s[2 * ks][0], s[2 * ks][1]));
            pa[0] = *(uint32_t*)&t;
            t = __float22bfloat162_rn(make_float2(s[2 * ks][2], s[2 * ks][3]));
            pa[1] = *(uint32_t*)&t;
            t = __float22bfloat162_rn(make_float2(s[2 * ks + 1][0], s[2 * ks + 1][1]));
            pa[2] = *(uint32_t*)&t;
            t = __float22bfloat162_rn(make_float2(s[2 * ks + 1][2], s[2 * ks + 1][3]));
            pa[3] = *(uint32_t*)&t;
#pragma unroll
            for (int jp = 0; jp < 4; jp++) {
                uint32_t vb[4];
                uint32_t rv = cV + (uint32_t)((ks * 16 + (lane & 15)) * LQ
                                              + jp * 16 + ((lane >> 4) << 3)) * 2;
                LDSM_X4_T(vb, rv);
                MMA_BF16(o[2 * jp],     pa, vb + 0);
                MMA_BF16(o[2 * jp + 1], pa, vb + 2);
            }
        }
        __syncthreads();
        buf ^= 1;
    }

    // ---- write ctx (hi, lo) ----
    const float invA = 1.f / lA, invB = 1.f / lB;
    const int rA = q0 + wq0 + (lane >> 2) + b * S_;
    const int col0 = h * HD_ + 2 * (lane & 3);
#pragma unroll
    for (int j = 0; j < 8; j++) {
        size_t oa = (size_t)rA * D_ + col0 + j * 8;
        size_t ob = oa + 8 * (size_t)D_;
        float vA0 = o[j][0] * invA, vA1 = o[j][1] * invA;
        float vB0 = o[j][2] * invB, vB1 = o[j][3] * invB;
        __nv_bfloat16 hA0 = __float2bfloat16(vA0), hA1 = __float2bfloat16(vA1);
        __nv_bfloat16 hB0 = __float2bfloat16(vB0), hB1 = __float2bfloat16(vB1);
        *(__nv_bfloat162*)&ctx_hi[oa] = __halves2bfloat162(hA0, hA1);
        *(__nv_bfloat162*)&ctx_hi[ob] = __halves2bfloat162(hB0, hB1);
        *(__nv_bfloat162*)&ctx_lo[oa] = __halves2bfloat162(
            __float2bfloat16(vA0 - __bfloat162float(hA0)),
            __float2bfloat16(vA1 - __bfloat162float(hA1)));
        *(__nv_bfloat162*)&ctx_lo[ob] = __halves2bfloat162(
            __float2bfloat16(vB0 - __bfloat162float(hB0)),
            __float2bfloat16(vB1 - __bfloat162float(hB1)));
    }
}

// ---------------------------------------------------------------------------
// Fused residual + LayerNorm (+ optional hi/lo bf16 emit)
// ---------------------------------------------------------------------------
__global__ __launch_bounds__(256)
void add_ln_kernel(const float* __restrict__ x, const float* __restrict__ r,
                   const float* __restrict__ g, const float* __restrict__ bb,
                   float* __restrict__ out,
                   __nv_bfloat16* __restrict__ ohi, __nv_bfloat16* __restrict__ olo) {
    __shared__ float red[16];
    const int row = blockIdx.x;
    const int tid = threadIdx.x;

    float4 xv = ((const float4*)(x + (size_t)row * D_))[tid];
    float4 rv = ((const float4*)(r + (size_t)row * D_))[tid];
    float v0 = xv.x + rv.x, v1 = xv.y + rv.y, v2 = xv.z + rv.z, v3 = xv.w + rv.w;

    float s  = v0 + v1 + v2 + v3;
    float sq = v0 * v0 + v1 * v1 + v2 * v2 + v3 * v3;
#pragma unroll
    for (int o = 16; o >= 1; o >>= 1) {
        s  += __shfl_xor_sync(0xffffffffu, s,  o);
        sq += __shfl_xor_sync(0xffffffffu, sq, o);
    }
    int warp = tid >> 5, lane = tid & 31;
    if (lane == 0) { red[warp] = s; red[8 + warp] = sq; }
    __syncthreads();
    if (tid == 0) {
        float ts = 0.f, tq = 0.f;
#pragma unroll
        for (int i = 0; i < 8; i++) { ts += red[i]; tq += red[8 + i]; }
        float mean = ts * (1.0f / D_);
        float var  = tq * (1.0f / D_) - mean * mean;
        red[0] = mean;
        red[1] = rsqrtf(var + EPSLN);
    }
    __syncthreads();
    float mean = red[0], rstd = red[1];

    float4 gv = ((const float4*)g)[tid];
    float4 bv = ((const float4*)bb)[tid];
    float o0 = (v0 - mean) * rstd * gv.x + bv.x;
    float o1 = (v1 - mean) * rstd * gv.y + bv.y;
    float o2 = (v2 - mean) * rstd * gv.z + bv.z;
    float o3 = (v3 - mean) * rstd * gv.w + bv.w;
    ((float4*)(out + (size_t)row * D_))[tid] = make_float4(o0, o1, o2, o3);

    if (ohi) {
        __nv_bfloat16 h0 = __float2bfloat16(o0), h1 = __float2bfloat16(o1);
        __nv_bfloat16 h2 = __float2bfloat16(o2), h3 = __float2bfloat16(o3);
        size_t o = (size_t)row * D_ + tid * 4;
        *(__nv_bfloat162*)&ohi[o]     = __halves2bfloat162(h0, h1);
        *(__nv_bfloat162*)&ohi[o + 2] = __halves2bfloat162(h2, h3);
        *(__nv_bfloat162*)&olo[o]     = __halves2bfloat162(
            __float2bfloat16(o0 - __bfloat162float(h0)),
            __float2bfloat16(o1 - __bfloat162float(h1)));
        *(__nv_bfloat162*)&olo[o + 2] = __halves2bfloat162(
            __float2bfloat16(o2 - __bfloat162float(h2)),
            __float2bfloat16(o3 - __bfloat162float(h3)));
    }
}

// ---------------------------------------------------------------------------
// Host launcher
// ---------------------------------------------------------------------------
static inline void split_launch(const float* x, __nv_bfloat16* hi, __nv_bfloat16* lo, int n) {
    int n4 = n / 4;
    split_bf16_kernel<<<(n4 + 255) / 256, 256>>>(x, hi, lo, n4);
}

extern "C" void kernel_launch(void* const* d_in, const int* in_sizes, int n_in,
                              void* d_out, int out_size) {
    const float* src    = (const float*)d_in[0];
    const float* qkv_w  = (const float*)d_in[1];
    const float* qkv_b  = (const float*)d_in[2];
    const float* out_w  = (const float*)d_in[3];
    const float* out_b  = (const float*)d_in[4];
    const float* ffn_w1 = (const float*)d_in[5];
    const float* ffn_b1 = (const float*)d_in[6];
    const float* ffn_w2 = (const float*)d_in[7];
    const float* ffn_b2 = (const float*)d_in[8];
    const float* ln1_g  = (const float*)d_in[9];
    const float* ln1_b  = (const float*)d_in[10];
    const float* ln2_g  = (const float*)d_in[11];
    const float* ln2_b  = (const float*)d_in[12];
    float* out = (float*)d_out;

    float *tmp, *agg;
    __nv_bfloat16 *qkvh;
    __nv_bfloat16 *src_hi, *src_lo, *ctx_hi, *ctx_lo, *agg_hi, *agg_lo, *h1_hi, *h1_lo;
    __nv_bfloat16 *wqkv_hi, *wqkv_lo, *wout_hi, *wout_lo, *wf1_hi, *wf1_lo, *wf2_hi, *wf2_lo;
    cudaGetSymbolAddress((void**)&tmp, g_tmp);
    cudaGetSymbolAddress((void**)&agg, g_agg);
    cudaGetSymbolAddress((void**)&qkvh, g_qkvh);
    cudaGetSymbolAddress((void**)&src_hi, g_src_hi);
    cudaGetSymbolAddress((void**)&src_lo, g_src_lo);
    cudaGetSymbolAddress((void**)&ctx_hi, g_ctx_hi);
    cudaGetSymbolAddress((void**)&ctx_lo, g_ctx_lo);
    cudaGetSymbolAddress((void**)&agg_hi, g_agg_hi);
    cudaGetSymbolAddress((void**)&agg_lo, g_agg_lo);
    cudaGetSymbolAddress((void**)&h1_hi, g_h1_hi);
    cudaGetSymbolAddress((void**)&h1_lo, g_h1_lo);
    cudaGetSymbolAddress((void**)&wqkv_hi, g_wqkv_hi);
    cudaGetSymbolAddress((void**)&wqkv_lo, g_wqkv_lo);
    cudaGetSymbolAddress((void**)&wout_hi, g_wout_hi);
    cudaGetSymbolAddress((void**)&wout_lo, g_wout_lo);
    cudaGetSymbolAddress((void**)&wf1_hi, g_wf1_hi);
    cudaGetSymbolAddress((void**)&wf1_lo, g_wf1_lo);
    cudaGetSymbolAddress((void**)&wf2_hi, g_wf2_hi);
    cudaGetSymbolAddress((void**)&wf2_lo, g_wf2_lo);

    cudaFuncSetAttribute(flash_mma,
                         cudaFuncAttributeMaxDynamicSharedMemorySize, FLASH_SMEM);
    cudaFuncSetAttribute(gemm_mma,
                         cudaFuncAttributeMaxDynamicSharedMemorySize, GEMM_SMEM);

    // Split inputs to (hi, lo) bf16
    split_launch(src, src_hi, src_lo, NTOK * D_);
    split_launch(qkv_w, wqkv_hi, wqkv_lo, 3 * D_ * D_);
    split_launch(out_w, wout_hi, wout_lo, D_ * D_);
    split_launch(ffn_w1, wf1_hi, wf1_lo, F_ * D_);
    split_launch(ffn_w2, wf2_hi, wf2_lo, D_ * F_);

    // 1. QKV projection -> bf16 (hi only; flash consumes bf16)
    gemm_mma<<<dim3(3 * D_ / 128, NTOK / 128), 256, GEMM_SMEM>>>(
        src_hi, src_lo, wqkv_hi, wqkv_lo, qkv_b, nullptr, qkvh, nullptr,
        NTOK, 3 * D_, D_, 0);

    // 2. Tensor-core flash attention -> ctx (hi, lo)
    flash_mma<<<dim3(S_ / 128, B_ * H_), 256, FLASH_SMEM>>>(qkvh, ctx_hi, ctx_lo);

    // 3. Output projection -> tmp (mha_out fp32)
    gemm_mma<<<dim3(D_ / 128, NTOK / 128), 256, GEMM_SMEM>>>(
        ctx_hi, ctx_lo, wout_hi, wout_lo, out_b, tmp, nullptr, nullptr,
        NTOK, D_, D_, 0);

    // 4. agg = LN1(src + mha_out) (+ hi/lo)
    add_ln_kernel<<<NTOK, 256>>>(src, tmp, ln1_g, ln1_b, agg, agg_hi, agg_lo);

    // 5. FFN1 + ReLU -> h1 (hi/lo)
    gemm_mma<<<dim3(F_ / 128, NTOK / 128), 256, GEMM_SMEM>>>(
        agg_hi, agg_lo, wf1_hi, wf1_lo, ffn_b1, nullptr, h1_hi, h1_lo,
        NTOK, F_, D_, 1);

    // 6. FFN2 -> tmp (ffn_out fp32)
    gemm_mma<<<dim3(D_ / 128, NTOK / 128), 256, GEMM_SMEM>>>(
        h1_hi, h1_lo, wf2_hi, wf2_lo, ffn_b2, tmp, nullptr, nullptr,
        NTOK, D_, F_, 0);

    // 7. out = LN2(agg + ffn_out)
    add_ln_kernel<<<NTOK, 256>>>(agg, tmp, ln2_g, ln2_b, out, nullptr, nullptr);
}